// round 13
// baseline (speedup 1.0000x reference)
#include <cuda_runtime.h>
#include <cuda_bf16.h>

// AMSoftmaxLoss: score (2048 x 50257) fp32, labels (2048) int32 in {0,1}
// R11 champion (row per block, 4-deep LDG.128, fused finale) with occupancy
// forced to 7 via smem footprint: 148*7 = 1036 slots -> 2048 rows = 1.977
// waves (quantization loss ~1.2% instead of 13.5%).

#define NROWS 2048
#define CCOLS 50257
#define BLK   256

// > 228KB/8 forces <= 7 resident blocks/SM; 7*29696B = 203KB fits.
#define SMEM_PAD_BYTES 29696

__device__ float g_rowL[NROWS];
__device__ unsigned int g_count = 0;   // self-resetting via atomicInc wrap

__device__ __forceinline__ float ex2f(float x) {
    float y;
    asm("ex2.approx.ftz.f32 %0, %1;" : "=f"(y) : "f"(x));
    return y;
}

#define SL2E (30.0f * 1.44269504088896340736f)   // S * log2(e)

struct SmemBlob {
    float  red[BLK];
    double dred[BLK];
    unsigned s_last;
    char pad[SMEM_PAD_BYTES - sizeof(float) * BLK - sizeof(double) * BLK - 16];
};

__global__ __launch_bounds__(BLK) void amsm_kernel(
    const float* __restrict__ score,
    const int* __restrict__ labels,
    float* __restrict__ out)
{
    __shared__ SmemBlob sm;

    const int row = blockIdx.x;
    const int tid = threadIdx.x;
    const float* __restrict__ p = score + (size_t)row * CCOLS;

    // Row base is (row mod 4) floats off 16B alignment (50257 % 4 == 1).
    const int peel = (4 - (row & 3)) & 3;

    float s0 = 0.f, s1 = 0.f, s2 = 0.f, s3 = 0.f;
    if (tid < peel) s0 += ex2f(SL2E * p[tid]);

    const int n4 = (CCOLS - peel) >> 2;
    const float4* __restrict__ q = (const float4*)(p + peel);

    int i = tid;
    // 4 x LDG.128 in flight per thread
    for (; i + 3 * BLK < n4; i += 4 * BLK) {
        float4 a = q[i];
        float4 b = q[i + BLK];
        float4 c = q[i + 2 * BLK];
        float4 d = q[i + 3 * BLK];
        s0 += ex2f(SL2E * a.x); s1 += ex2f(SL2E * a.y);
        s2 += ex2f(SL2E * a.z); s3 += ex2f(SL2E * a.w);
        s0 += ex2f(SL2E * b.x); s1 += ex2f(SL2E * b.y);
        s2 += ex2f(SL2E * b.z); s3 += ex2f(SL2E * b.w);
        s0 += ex2f(SL2E * c.x); s1 += ex2f(SL2E * c.y);
        s2 += ex2f(SL2E * c.z); s3 += ex2f(SL2E * c.w);
        s0 += ex2f(SL2E * d.x); s1 += ex2f(SL2E * d.y);
        s2 += ex2f(SL2E * d.z); s3 += ex2f(SL2E * d.w);
    }
    for (; i < n4; i += BLK) {
        float4 a = q[i];
        s0 += ex2f(SL2E * a.x); s1 += ex2f(SL2E * a.y);
        s2 += ex2f(SL2E * a.z); s3 += ex2f(SL2E * a.w);
    }
    const int tail = peel + 4 * n4;
    if (tid < CCOLS - tail) s0 += ex2f(SL2E * p[tail + tid]);

    float sum = (s0 + s1) + (s2 + s3);

    // Block reduction
    sm.red[tid] = sum;
    __syncthreads();
    #pragma unroll
    for (int off = BLK / 2; off >= 32; off >>= 1) {
        if (tid < off) sm.red[tid] += sm.red[tid + off];
        __syncthreads();
    }

    if (tid < 32) {
        float v = sm.red[tid];
        #pragma unroll
        for (int off = 16; off > 0; off >>= 1)
            v += __shfl_down_sync(0xFFFFFFFFu, v, off);
        if (tid == 0) {
            int lab = labels[row] & 1;             // 0 or 1
            float m = lab ? 0.4f : 0.1f;
            float t = p[lab];                      // target logit
            float num = 30.0f * (t - m);
            float excl = v - ex2f(SL2E * t);       // sum minus target term
            float denom = ex2f(num * 1.44269504088896340736f) + excl;
            g_rowL[row] = num - logf(denom);
            __threadfence();
            unsigned old = atomicInc(&g_count, NROWS - 1);  // wraps -> reset
            sm.s_last = (old == NROWS - 1) ? 1u : 0u;
        }
    }
    __syncthreads();

    // Last-arriving block reduces all row losses and writes the output.
    if (sm.s_last) {
        volatile float* rl = g_rowL;
        double acc = 0.0;
        for (int r = tid; r < NROWS; r += BLK)
            acc += (double)rl[r];
        sm.dred[tid] = acc;
        __syncthreads();
        #pragma unroll
        for (int off = BLK / 2; off > 0; off >>= 1) {
            if (tid < off) sm.dred[tid] += sm.dred[tid + off];
            __syncthreads();
        }
        if (tid == 0)
            out[0] = (float)(-sm.dred[0] / (double)NROWS);
    }
}

extern "C" void kernel_launch(void* const* d_in, const int* in_sizes, int n_in,
                              void* d_out, int out_size)
{
    const float* score = (const float*)d_in[0];
    const int* labels = (const int*)d_in[1];
    float* out = (float*)d_out;

    amsm_kernel<<<NROWS, BLK>>>(score, labels, out);
}

// round 14
// speedup vs baseline: 1.1999x; 1.1999x over previous
#include <cuda_runtime.h>
#include <cuda_bf16.h>

// AMSoftmaxLoss: score (2048 x 50257) fp32, labels (2048) int32 in {0,1}
// 8192 quarter-row blocks (98.8% wave utilization at occ 8), 4-deep plain
// LDG.128 inner loop, per-block partial -> g_part, last-arriving block
// folds 4 partials/row + epilogue.

#define NROWS 2048
#define CCOLS 50257
#define BLK   256
#define SEGS  4
#define SEGW  12565            // 3*12565 + 12562 = 50257
#define NTILES (NROWS * SEGS)  // 8192

__device__ float g_part[NTILES];
__device__ unsigned int g_count = 0;   // self-resetting via atomicInc wrap

__device__ __forceinline__ float ex2f(float x) {
    float y;
    asm("ex2.approx.ftz.f32 %0, %1;" : "=f"(y) : "f"(x));
    return y;
}

#define SL2E (30.0f * 1.44269504088896340736f)   // S * log2(e)

__global__ __launch_bounds__(BLK) void amsm_kernel(
    const float* __restrict__ score,
    const int* __restrict__ labels,
    float* __restrict__ out)
{
    const int t    = blockIdx.x;
    const int tid  = threadIdx.x;
    const int lane = tid & 31;
    const int wid  = tid >> 5;

    const int r    = t >> 2;
    const int seg  = t & 3;
    const int col0 = seg * SEGW;
    const int len  = (seg == SEGS - 1) ? (CCOLS - col0) : SEGW;
    const float* __restrict__ p = score + (size_t)r * CCOLS + col0;

    float s0 = 0.f, s1 = 0.f, s2 = 0.f, s3 = 0.f;

    int peel = (-(r * CCOLS + col0)) & 3;          // to 16B alignment
    if (tid < peel) s0 += ex2f(SL2E * p[tid]);

    const int n4 = (len - peel) >> 2;
    const float4* __restrict__ q = (const float4*)(p + peel);

    int i = tid;
    for (; i + 3 * BLK < n4; i += 4 * BLK) {       // 4 LDG.128 in flight
        float4 a = q[i];
        float4 b = q[i + BLK];
        float4 c = q[i + 2 * BLK];
        float4 d = q[i + 3 * BLK];
        s0 += ex2f(SL2E * a.x); s1 += ex2f(SL2E * a.y);
        s2 += ex2f(SL2E * a.z); s3 += ex2f(SL2E * a.w);
        s0 += ex2f(SL2E * b.x); s1 += ex2f(SL2E * b.y);
        s2 += ex2f(SL2E * b.z); s3 += ex2f(SL2E * b.w);
        s0 += ex2f(SL2E * c.x); s1 += ex2f(SL2E * c.y);
        s2 += ex2f(SL2E * c.z); s3 += ex2f(SL2E * c.w);
        s0 += ex2f(SL2E * d.x); s1 += ex2f(SL2E * d.y);
        s2 += ex2f(SL2E * d.z); s3 += ex2f(SL2E * d.w);
    }
    for (; i < n4; i += BLK) {
        float4 a = q[i];
        s0 += ex2f(SL2E * a.x); s1 += ex2f(SL2E * a.y);
        s2 += ex2f(SL2E * a.z); s3 += ex2f(SL2E * a.w);
    }
    const int done = peel + 4 * n4;
    if (tid < len - done) s0 += ex2f(SL2E * p[done + tid]);

    float v = (s0 + s1) + (s2 + s3);

    // Block reduction: warp shuffle then cross-warp via smem.
    __shared__ float wsum[BLK / 32];
    #pragma unroll
    for (int off = 16; off > 0; off >>= 1)
        v += __shfl_down_sync(0xFFFFFFFFu, v, off);
    if (lane == 0) wsum[wid] = v;
    __syncthreads();

    __shared__ unsigned s_last;
    if (tid == 0) {
        float w = 0.f;
        #pragma unroll
        for (int k = 0; k < BLK / 32; k++) w += wsum[k];
        g_part[t] = w;
        __threadfence();
        unsigned old = atomicInc(&g_count, NTILES - 1);  // wraps -> self-reset
        s_last = (old == NTILES - 1) ? 1u : 0u;
    }
    __syncthreads();
    if (!s_last) return;

    // ---- Last-arriving block: fold partials, per-row epilogue, mean ----
    volatile float* gp = g_part;
    double acc = 0.0;
    for (int r2 = tid; r2 < NROWS; r2 += BLK) {
        float rs = (gp[4 * r2] + gp[4 * r2 + 1]) + (gp[4 * r2 + 2] + gp[4 * r2 + 3]);

        int lab = labels[r2] & 1;
        float m = lab ? 0.4f : 0.1f;
        float tg = __ldg(score + (size_t)r2 * CCOLS + lab);
        float num = 30.0f * (tg - m);
        float excl = rs - ex2f(SL2E * tg);
        float denom = ex2f(num * 1.44269504088896340736f) + excl;
        acc += (double)(num - logf(denom));
    }

    __shared__ double dred[BLK];
    dred[tid] = acc;
    __syncthreads();
    #pragma unroll
    for (int off = BLK / 2; off > 0; off >>= 1) {
        if (tid < off) dred[tid] += dred[tid + off];
        __syncthreads();
    }
    if (tid == 0)
        out[0] = (float)(-dred[0] / (double)NROWS);
}

extern "C" void kernel_launch(void* const* d_in, const int* in_sizes, int n_in,
                              void* d_out, int out_size)
{
    const float* score = (const float*)d_in[0];
    const int* labels = (const int*)d_in[1];
    float* out = (float*)d_out;

    amsm_kernel<<<NTILES, BLK>>>(score, labels, out);
}

// round 15
// speedup vs baseline: 1.2434x; 1.0363x over previous
#include <cuda_runtime.h>
#include <cuda_bf16.h>

// AMSoftmaxLoss: score (2048 x 50257) fp32, labels (2048) int32 in {0,1}
// R11 structure (one block per row, fused finale) with the register load
// pipeline replaced by a per-thread 5-stage cp.async.cg ring in SMEM:
// deeper in-flight bytes, zero block syncs in the hot loop, occ-8 kept.

#define NROWS 2048
#define CCOLS 50257
#define BLK   256
#define STAGES 5

__device__ float g_rowL[NROWS];
__device__ unsigned int g_count = 0;   // self-resetting via atomicInc wrap

__device__ __forceinline__ float ex2f(float x) {
    float y;
    asm("ex2.approx.ftz.f32 %0, %1;" : "=f"(y) : "f"(x));
    return y;
}

#define SL2E (30.0f * 1.44269504088896340736f)   // S * log2(e)

#define CP_ASYNC16(dst_u32, src_ptr) \
    asm volatile("cp.async.cg.shared.global [%0], [%1], 16;" \
                 :: "r"(dst_u32), "l"(src_ptr))
#define CP_COMMIT() asm volatile("cp.async.commit_group;")
#define CP_WAIT(n)  asm volatile("cp.async.wait_group %0;" :: "n"(n))

__global__ __launch_bounds__(BLK) void amsm_kernel(
    const float* __restrict__ score,
    const int* __restrict__ labels,
    float* __restrict__ out)
{
    __shared__ float4 buf[STAGES][BLK];      // 20 KB ring
    __shared__ float red[BLK];
    __shared__ double dred[BLK];
    __shared__ unsigned s_last;

    const int row = blockIdx.x;
    const int tid = threadIdx.x;
    const float* __restrict__ p = score + (size_t)row * CCOLS;

    // Row base is (row mod 4) floats off 16B alignment (50257 % 4 == 1).
    const int peel = (4 - (row & 3)) & 3;

    float s0 = 0.f, s1 = 0.f, s2 = 0.f, s3 = 0.f;
    if (tid < peel) s0 += ex2f(SL2E * p[tid]);

    const int n4 = (CCOLS - peel) >> 2;
    const float4* __restrict__ q = (const float4*)(p + peel);
    const int nStages = (n4 + BLK - 1) / BLK;            // ~50

    const unsigned sbase =
        (unsigned)__cvta_generic_to_shared(&buf[0][tid]);

    // Prologue: issue up to STAGES stages (guarded), always commit.
    #pragma unroll
    for (int s = 0; s < STAGES; s++) {
        int idx = tid + s * BLK;
        if (idx < n4) CP_ASYNC16(sbase + s * (BLK * 16), q + idx);
        CP_COMMIT();
    }

    // Main loop: wait oldest stage, consume own 16B, refill slot. No syncs.
    int slot = 0;
    for (int k = 0; k < nStages; k++) {
        CP_WAIT(STAGES - 1);                 // stage k's group complete
        const int idx = tid + k * BLK;
        if (idx < n4) {
            float4 a = buf[slot][tid];
            s0 += ex2f(SL2E * a.x); s1 += ex2f(SL2E * a.y);
            s2 += ex2f(SL2E * a.z); s3 += ex2f(SL2E * a.w);
        }
        const int in = idx + STAGES * BLK;
        if (in < n4) CP_ASYNC16(sbase + slot * (BLK * 16), q + in);
        CP_COMMIT();
        slot = (slot == STAGES - 1) ? 0 : slot + 1;
    }

    const int tail = peel + 4 * n4;          // < 4 leftover elements
    if (tid < CCOLS - tail) s0 += ex2f(SL2E * p[tail + tid]);

    float sum = (s0 + s1) + (s2 + s3);

    // Block reduction
    red[tid] = sum;
    __syncthreads();
    #pragma unroll
    for (int off = BLK / 2; off >= 32; off >>= 1) {
        if (tid < off) red[tid] += red[tid + off];
        __syncthreads();
    }

    if (tid < 32) {
        float v = red[tid];
        #pragma unroll
        for (int off = 16; off > 0; off >>= 1)
            v += __shfl_down_sync(0xFFFFFFFFu, v, off);
        if (tid == 0) {
            int lab = labels[row] & 1;             // 0 or 1
            float m = lab ? 0.4f : 0.1f;
            float t = p[lab];                      // target logit
            float num = 30.0f * (t - m);
            float excl = v - ex2f(SL2E * t);       // sum minus target term
            float denom = ex2f(num * 1.44269504088896340736f) + excl;
            g_rowL[row] = num - logf(denom);
            __threadfence();
            unsigned old = atomicInc(&g_count, NROWS - 1);  // wraps -> reset
            s_last = (old == NROWS - 1) ? 1u : 0u;
        }
    }
    __syncthreads();

    // Last-arriving block reduces all row losses and writes the output.
    if (s_last) {
        volatile float* rl = g_rowL;
        double acc = 0.0;
        for (int r = tid; r < NROWS; r += BLK)
            acc += (double)rl[r];
        dred[tid] = acc;
        __syncthreads();
        #pragma unroll
        for (int off = BLK / 2; off > 0; off >>= 1) {
            if (tid < off) dred[tid] += dred[tid + off];
            __syncthreads();
        }
        if (tid == 0)
            out[0] = (float)(-dred[0] / (double)NROWS);
    }
}

extern "C" void kernel_launch(void* const* d_in, const int* in_sizes, int n_in,
                              void* d_out, int out_size)
{
    const float* score = (const float*)d_in[0];
    const int* labels = (const int*)d_in[1];
    float* out = (float*)d_out;

    amsm_kernel<<<NROWS, BLK>>>(score, labels, out);
}